// round 3
// baseline (speedup 1.0000x reference)
#include <cuda_runtime.h>
#include <math.h>

// Problem maxima (actual sizes read from in_sizes at runtime)
#define NMAX 40960
#define EMAX 602112
#define HDIM 128

// ---------------- scratch (device globals: allocation-free) ----------------
__device__ __align__(16) float g_h[NMAX * HDIM];   // layer output / current features
__device__ __align__(16) float g_a[NMAX * HDIM];   // agg result / mid buffer
__device__ __align__(16) float g_b[NMAX * HDIM];   // mid buffer
__device__ int g_src[EMAX];
__device__ int g_dst[EMAX];
__device__ int g_eidx[EMAX];                       // CSR column indices (src sorted by dst)
__device__ int g_deg[NMAX];
__device__ int g_rowptr[NMAX + 1];
__device__ int g_fill[NMAX];
__device__ int g_is64;

// ---------------- edge dtype detection + conversion ----------------
// If edge_index is int64 (little-endian, values < 2^31), every odd 32-bit word
// of the buffer is zero. For int32 data (random values in [0,40000)) that is
// essentially impossible across 64 samples.
__global__ void k_detect(const unsigned int* __restrict__ w) {
    if (threadIdx.x == 0 && blockIdx.x == 0) {
        int ok = 1;
        for (int i = 0; i < 64; i++)
            if (w[2 * i + 1] != 0u) ok = 0;
        g_is64 = ok;
    }
}

__global__ void k_convert(const int* __restrict__ w, int E) {
    int i = blockIdx.x * blockDim.x + threadIdx.x;
    if (i >= E) return;
    if (g_is64) {
        g_src[i] = w[2 * i];
        g_dst[i] = w[2 * (E + i)];
    } else {
        g_src[i] = w[i];
        g_dst[i] = w[E + i];
    }
}

// ---------------- CSR build ----------------
__global__ void k_zero_deg(int N) {
    int i = blockIdx.x * blockDim.x + threadIdx.x;
    if (i < N) g_deg[i] = 0;
}

__global__ void k_count(int E) {
    int i = blockIdx.x * blockDim.x + threadIdx.x;
    if (i >= E) return;
    atomicAdd(&g_deg[g_dst[i]], 1);
}

// single-block exclusive scan over g_deg -> g_rowptr[0..N]
__global__ void k_scan(int N) {
    __shared__ int sm[1024];
    __shared__ int carry_s;
    int tid = threadIdx.x;
    if (tid == 0) carry_s = 0;
    __syncthreads();
    for (int base = 0; base < N; base += 1024) {
        int v = (base + tid < N) ? g_deg[base + tid] : 0;
        sm[tid] = v;
        __syncthreads();
        for (int off = 1; off < 1024; off <<= 1) {
            int t = (tid >= off) ? sm[tid - off] : 0;
            __syncthreads();
            sm[tid] += t;
            __syncthreads();
        }
        int incl = sm[tid] + carry_s;
        if (base + tid < N) g_rowptr[base + tid + 1] = incl;
        __syncthreads();
        if (tid == 0) carry_s += sm[1023];
        __syncthreads();
    }
    if (tid == 0) g_rowptr[0] = 0;
}

__global__ void k_copyfill(int N) {
    int i = blockIdx.x * blockDim.x + threadIdx.x;
    if (i < N) g_fill[i] = g_rowptr[i];
}

__global__ void k_fill(int E) {
    int i = blockIdx.x * blockDim.x + threadIdx.x;
    if (i >= E) return;
    int pos = atomicAdd(&g_fill[g_dst[i]], 1);
    g_eidx[pos] = g_src[i];
}

// ---------------- aggregation: out[i] = x[i] + sum_{j in N(i)} x[j] ----------------
// one warp per node; lane = one float4 of the 128-dim feature row
__global__ void __launch_bounds__(256) k_agg(const float* __restrict__ xin,
                                             float* __restrict__ out, int N) {
    int warp = (blockIdx.x * blockDim.x + threadIdx.x) >> 5;
    int lane = threadIdx.x & 31;
    if (warp >= N) return;
    const float4* xv = (const float4*)xin;
    float4 acc = xv[(size_t)warp * 32 + lane];
    int beg = g_rowptr[warp];
    int end = g_rowptr[warp + 1];
    for (int e = beg; e < end; e++) {
        int s = g_eidx[e];
        float4 v = xv[(size_t)s * 32 + lane];
        acc.x += v.x; acc.y += v.y; acc.z += v.z; acc.w += v.w;
    }
    ((float4*)out)[(size_t)warp * 32 + lane] = acc;
}

// ---------------- fused GEMM + epilogue ----------------
// out[M, NC] = A[M,128] @ W[128, NC] + epilogue
//   EPI=0: +bias, BatchNorm(mu,var,g,bt), ELU
//   EPI=1: +bias, ELU
//   EPI=2: +bias
// NC = 16*TN; 256 threads; BM=128; thread tile 8 x TN.
__device__ __forceinline__ float elu_f(float x) { return x > 0.f ? x : expm1f(x); }

template <int TN, int EPI>
__global__ void __launch_bounds__(256) k_gemm(
    const float* __restrict__ A, const float* __restrict__ W,
    const float* __restrict__ bias,
    const float* __restrict__ gam, const float* __restrict__ bet,
    const float* __restrict__ mu, const float* __restrict__ var,
    float* __restrict__ out, int M)
{
    constexpr int NC = 16 * TN;
    __shared__ float As[128][33];      // pad 33: conflict-free stores + broadcast reads
    __shared__ float Ws[32][NC];

    const int tid = threadIdx.x;
    const int tx = tid & 15;           // 16 column groups
    const int ty = tid >> 4;           // 16 row groups (8 rows each)
    const int row_base = blockIdx.x * 128;

    float acc[8][TN];
#pragma unroll
    for (int r = 0; r < 8; r++)
#pragma unroll
        for (int j = 0; j < TN; j++) acc[r][j] = 0.f;

#pragma unroll
    for (int kc = 0; kc < 4; kc++) {   // K=128 in 4 chunks of 32
        // --- load A chunk: 128 rows x 32 k ---
#pragma unroll
        for (int i = 0; i < 4; i++) {
            int f = tid + 256 * i;     // 0..1023 float4 slots
            int r = f >> 3;            // row in tile
            int kq = f & 7;            // float4 index within chunk
            float4 v = make_float4(0.f, 0.f, 0.f, 0.f);
            if (row_base + r < M)
                v = *(const float4*)(A + (size_t)(row_base + r) * 128 + kc * 32 + kq * 4);
            As[r][kq * 4 + 0] = v.x;
            As[r][kq * 4 + 1] = v.y;
            As[r][kq * 4 + 2] = v.z;
            As[r][kq * 4 + 3] = v.w;
        }
        // --- load W chunk: 32 k x NC ---
#pragma unroll
        for (int i = 0; i < NC / 32; i++) {
            int f = tid + 256 * i;
            int n4 = f % (NC / 4);
            int kk = f / (NC / 4);
            float4 v = *(const float4*)(W + (size_t)(kc * 32 + kk) * NC + n4 * 4);
            *(float4*)&Ws[kk][n4 * 4] = v;
        }
        __syncthreads();

#pragma unroll
        for (int kk = 0; kk < 32; kk++) {
            float a[8];
#pragma unroll
            for (int r = 0; r < 8; r++) a[r] = As[ty * 8 + r][kk];
            float w[TN];
#pragma unroll
            for (int q = 0; q < TN / 4; q++) {
                float4 wv = *(const float4*)&Ws[kk][tx * TN + q * 4];
                w[q * 4 + 0] = wv.x; w[q * 4 + 1] = wv.y;
                w[q * 4 + 2] = wv.z; w[q * 4 + 3] = wv.w;
            }
#pragma unroll
            for (int r = 0; r < 8; r++)
#pragma unroll
                for (int j = 0; j < TN; j++) acc[r][j] += a[r] * w[j];
        }
        __syncthreads();
    }

    // --- epilogue ---
    float scl[TN], shf[TN];
#pragma unroll
    for (int j = 0; j < TN; j++) {
        int n = tx * TN + j;
        if (EPI == 0) {
            float s = gam[n] * rsqrtf(var[n] + 1e-5f);
            scl[j] = s;
            shf[j] = (bias[n] - mu[n]) * s + bet[n];
        } else {
            scl[j] = 1.f;
            shf[j] = bias[n];
        }
    }
#pragma unroll
    for (int r = 0; r < 8; r++) {
        int row = row_base + ty * 8 + r;
        if (row < M) {
#pragma unroll
            for (int j = 0; j < TN; j++) {
                float v = acc[r][j] * scl[j] + shf[j];
                if (EPI <= 1) v = elu_f(v);
                out[(size_t)row * NC + tx * TN + j] = v;
            }
        }
    }
}

// ---------------- launch ----------------
extern "C" void kernel_launch(void* const* d_in, const int* in_sizes, int n_in,
                              void* d_out, int out_size) {
    const float* x = (const float*)d_in[0];
    const int* ei = (const int*)d_in[1];
    const int N = in_sizes[0] / HDIM;   // 40000
    const int E = in_sizes[1] / 2;      // 600000

    float *hP, *aP, *bP;
    cudaGetSymbolAddress((void**)&hP, g_h);
    cudaGetSymbolAddress((void**)&aP, g_a);
    cudaGetSymbolAddress((void**)&bP, g_b);

    const int EB = (E + 255) / 256;
    const int NB = (N + 255) / 256;
    const int GM = (N + 127) / 128;     // GEMM row tiles
    const int AGB = (N + 7) / 8;        // agg: 8 warps/block

    // CSR build (edge_index is constant across calls, but rebuild keeps us
    // deterministic & stateless; cost ~15us)
    k_detect<<<1, 32>>>((const unsigned int*)ei);
    k_convert<<<EB, 256>>>(ei, E);
    k_zero_deg<<<NB, 256>>>(N);
    k_count<<<EB, 256>>>(E);
    k_scan<<<1, 1024>>>(N);
    k_copyfill<<<NB, 256>>>(N);
    k_fill<<<EB, 256>>>(E);

    // 3x GINConv
    const float* cur = x;
    for (int l = 0; l < 3; l++) {
        const float* w1  = (const float*)d_in[2 + l * 8 + 0];
        const float* b1  = (const float*)d_in[2 + l * 8 + 1];
        const float* gmm = (const float*)d_in[2 + l * 8 + 2];
        const float* btt = (const float*)d_in[2 + l * 8 + 3];
        const float* muu = (const float*)d_in[2 + l * 8 + 4];
        const float* vrr = (const float*)d_in[2 + l * 8 + 5];
        const float* w2  = (const float*)d_in[2 + l * 8 + 6];
        const float* b2  = (const float*)d_in[2 + l * 8 + 7];

        k_agg<<<AGB, 256>>>(cur, aP, N);
        k_gemm<8, 0><<<GM, 256>>>(aP, w1, b1, gmm, btt, muu, vrr, bP, N);
        k_gemm<8, 1><<<GM, 256>>>(bP, w2, b2, nullptr, nullptr, nullptr, nullptr, hP, N);
        cur = hP;
    }

    // lin1 + ELU, then lin2 (128 -> 64) into d_out
    const float* l1w = (const float*)d_in[26];
    const float* l1b = (const float*)d_in[27];
    const float* l2w = (const float*)d_in[28];
    const float* l2b = (const float*)d_in[29];

    k_gemm<8, 1><<<GM, 256>>>(hP, l1w, l1b, nullptr, nullptr, nullptr, nullptr, aP, N);
    k_gemm<4, 2><<<GM, 256>>>(aP, l2w, l2b, nullptr, nullptr, nullptr, nullptr,
                              (float*)d_out, N);
}

// round 4
// speedup vs baseline: 1.6094x; 1.6094x over previous
#include <cuda_runtime.h>
#include <math.h>

#define NMAX 40960
#define EMAX 602112
#define HDIM 128

// ---------------- scratch (device globals: allocation-free) ----------------
__device__ __align__(16) float g_h[NMAX * HDIM];
__device__ __align__(16) float g_a[NMAX * HDIM];
__device__ __align__(16) float g_b[NMAX * HDIM];
__device__ int g_src[EMAX];
__device__ int g_dst[EMAX];
__device__ int g_eidx[EMAX];
__device__ int g_deg[NMAX];
__device__ int g_rowptr[NMAX + 1];
__device__ int g_fill[NMAX];
__device__ int g_is64;
// packed tf32 hi/lo weight fragments: stages 0..6 are 128x128 (8192 float4 each),
// stage 7 is 128x64 (4096 float4). total 61440 float4.
__device__ __align__(16) float4 g_wpk[61440];
__device__ float g_escl[8][128];
__device__ float g_eshf[8][128];

// ---------------- helpers ----------------
__device__ __forceinline__ unsigned tf32r(float f) {
    unsigned u;
    asm("cvt.rna.tf32.f32 %0, %1;" : "=r"(u) : "f"(f));
    return u;
}

__device__ __forceinline__ void mma_tf32(float* c, const unsigned* a,
                                         unsigned b0, unsigned b1) {
    asm volatile(
        "mma.sync.aligned.m16n8k8.row.col.f32.tf32.tf32.f32 "
        "{%0,%1,%2,%3}, {%4,%5,%6,%7}, {%8,%9}, {%0,%1,%2,%3};\n"
        : "+f"(c[0]), "+f"(c[1]), "+f"(c[2]), "+f"(c[3])
        : "r"(a[0]), "r"(a[1]), "r"(a[2]), "r"(a[3]), "r"(b0), "r"(b1));
}

__device__ __forceinline__ float elu_f(float x) { return x > 0.f ? x : expm1f(x); }

// ---------------- edge dtype detection ----------------
__global__ void k_detect(const unsigned int* __restrict__ w) {
    if (threadIdx.x == 0 && blockIdx.x == 0) {
        int ok = 1;
        for (int i = 0; i < 64; i++)
            if (w[2 * i + 1] != 0u) ok = 0;
        g_is64 = ok;
    }
}

__global__ void k_zero_deg(int N) {
    int i = blockIdx.x * blockDim.x + threadIdx.x;
    if (i < N) g_deg[i] = 0;
}

// convert + degree count fused
__global__ void k_convcount(const int* __restrict__ w, int E) {
    int i = blockIdx.x * blockDim.x + threadIdx.x;
    if (i >= E) return;
    int s, d;
    if (g_is64) { s = w[2 * i]; d = w[2 * (E + i)]; }
    else        { s = w[i];     d = w[E + i]; }
    g_src[i] = s;
    g_dst[i] = d;
    atomicAdd(&g_deg[d], 1);
}

// chunked single-block exclusive scan; also initializes g_fill
__global__ void k_scan(int N) {
    __shared__ int sums[1024];
    int tid = threadIdx.x;
    int chunk = (N + 1023) / 1024;
    int beg = tid * chunk;
    int end = beg + chunk; if (end > N) end = N;
    int s = 0;
    for (int i = beg; i < end; i++) s += g_deg[i];
    sums[tid] = s;
    __syncthreads();
    for (int off = 1; off < 1024; off <<= 1) {
        int v = (tid >= off) ? sums[tid - off] : 0;
        __syncthreads();
        sums[tid] += v;
        __syncthreads();
    }
    int run = (tid > 0) ? sums[tid - 1] : 0;
    for (int i = beg; i < end; i++) {
        g_rowptr[i] = run;
        g_fill[i] = run;
        run += g_deg[i];
    }
    if (tid == 0) g_rowptr[N] = sums[1023];
}

__global__ void k_fill(int E) {
    int i = blockIdx.x * blockDim.x + threadIdx.x;
    if (i >= E) return;
    int pos = atomicAdd(&g_fill[g_dst[i]], 1);
    g_eidx[pos] = g_src[i];
}

// ---------------- aggregation: out[i] = x[i] + sum_{j in N(i)} x[j] ----------------
__global__ void __launch_bounds__(256) k_agg(const float* __restrict__ xin,
                                             float* __restrict__ out, int N) {
    int warp = (blockIdx.x * blockDim.x + threadIdx.x) >> 5;
    int lane = threadIdx.x & 31;
    if (warp >= N) return;
    const float4* xv = (const float4*)xin;
    float4 acc = xv[(size_t)warp * 32 + lane];
    int beg = g_rowptr[warp];
    int end = g_rowptr[warp + 1];
    for (int e = beg; e < end; e++) {
        int s = g_eidx[e];
        float4 v = xv[(size_t)s * 32 + lane];
        acc.x += v.x; acc.y += v.y; acc.z += v.z; acc.w += v.w;
    }
    ((float4*)out)[(size_t)warp * 32 + lane] = acc;
}

// ---------------- weight packing: fragment-ordered tf32 hi/lo ----------------
struct PackArgs { const float* w[8]; };

__global__ void k_pack(PackArgs pa) {
    int fid = blockIdx.x * 256 + threadIdx.x;
    if (fid >= 61440) return;
    int s, rem, NTl;
    if (fid < 57344) { s = fid >> 13; rem = fid & 8191; NTl = 16; }
    else             { s = 7; rem = fid - 57344; NTl = 8; }
    int lane = rem & 31;
    int nt = (rem >> 5) % NTl;
    int kt = rem / (32 * NTl);
    int t = lane & 3, g = lane >> 2;
    int Ncol = NTl * 8;
    const float* W = pa.w[s];
    float b0 = W[(kt * 8 + t) * Ncol + nt * 8 + g];
    float b1 = W[(kt * 8 + t + 4) * Ncol + nt * 8 + g];
    unsigned h0 = tf32r(b0);
    unsigned l0 = tf32r(b0 - __uint_as_float(h0));
    unsigned h1 = tf32r(b1);
    unsigned l1 = tf32r(b1 - __uint_as_float(h1));
    g_wpk[fid] = make_float4(__uint_as_float(h0), __uint_as_float(h1),
                             __uint_as_float(l0), __uint_as_float(l1));
}

// ---------------- epilogue param precompute ----------------
struct EpsArgs {
    const float* bias[8];
    const float* gam[8];
    const float* bet[8];
    const float* mu[8];
    const float* var[8];
    int epi[8];
    int n[8];
};

__global__ void k_eps(EpsArgs ea) {
    int s = blockIdx.x;
    int c = threadIdx.x;
    if (c >= ea.n[s]) return;
    if (ea.epi[s] == 0) {
        float sc = ea.gam[s][c] * rsqrtf(ea.var[s][c] + 1e-5f);
        g_escl[s][c] = sc;
        g_eshf[s][c] = (ea.bias[s][c] - ea.mu[s][c]) * sc + ea.bet[s][c];
    } else {
        g_escl[s][c] = 1.f;
        g_eshf[s][c] = ea.bias[s][c];
    }
}

// ---------------- tensor-core GEMM (tf32 x3) + fused epilogue ----------------
// out[M, NT*8] = elu?(scl * (A[M,128] @ W) + shf)
// block = 128 threads (4 warps), each warp: 32 rows (2 m16 tiles) x all N cols.
template <int NT, bool DOELU>
__global__ void __launch_bounds__(128) k_tgemm(
    const float* __restrict__ A, const float4* __restrict__ WP4,
    const float* __restrict__ scl, const float* __restrict__ shf,
    float* __restrict__ out, int M)
{
    const int warp = threadIdx.x >> 5;
    const int lane = threadIdx.x & 31;
    const int g = lane >> 2, t = lane & 3;
    const int R = blockIdx.x * 128 + warp * 32;
    const int NCOL = NT * 8;

    float c[2][NT][4];
#pragma unroll
    for (int mi = 0; mi < 2; mi++)
#pragma unroll
        for (int nt = 0; nt < NT; nt++)
#pragma unroll
            for (int j = 0; j < 4; j++) c[mi][nt][j] = 0.f;

#pragma unroll 2
    for (int kt = 0; kt < 16; kt++) {
        unsigned ah[2][4], al[2][4];
#pragma unroll
        for (int mi = 0; mi < 2; mi++) {
            const float* Ap = A + (size_t)(R + mi * 16 + g) * 128 + kt * 8 + t;
            float a0 = Ap[0];
            float a1 = Ap[8 * 128];
            float a2 = Ap[4];
            float a3 = Ap[8 * 128 + 4];
            ah[mi][0] = tf32r(a0); al[mi][0] = tf32r(a0 - __uint_as_float(ah[mi][0]));
            ah[mi][1] = tf32r(a1); al[mi][1] = tf32r(a1 - __uint_as_float(ah[mi][1]));
            ah[mi][2] = tf32r(a2); al[mi][2] = tf32r(a2 - __uint_as_float(ah[mi][2]));
            ah[mi][3] = tf32r(a3); al[mi][3] = tf32r(a3 - __uint_as_float(ah[mi][3]));
        }
        const float4* wp = WP4 + (size_t)kt * NT * 32 + lane;
#pragma unroll
        for (int nt = 0; nt < NT; nt++) {
            float4 b = __ldg(&wp[nt * 32]);
            unsigned bh0 = __float_as_uint(b.x), bh1 = __float_as_uint(b.y);
            unsigned bl0 = __float_as_uint(b.z), bl1 = __float_as_uint(b.w);
#pragma unroll
            for (int mi = 0; mi < 2; mi++) {
                mma_tf32(c[mi][nt], ah[mi], bh0, bh1);
                mma_tf32(c[mi][nt], al[mi], bh0, bh1);
                mma_tf32(c[mi][nt], ah[mi], bl0, bl1);
            }
        }
    }

    // epilogue
#pragma unroll
    for (int nt = 0; nt < NT; nt++) {
        int col = nt * 8 + 2 * t;
        float2 sv = *(const float2*)(scl + col);
        float2 hv = *(const float2*)(shf + col);
#pragma unroll
        for (int mi = 0; mi < 2; mi++) {
            int r0 = R + mi * 16 + g;
            float v0 = c[mi][nt][0] * sv.x + hv.x;
            float v1 = c[mi][nt][1] * sv.y + hv.y;
            if (DOELU) { v0 = elu_f(v0); v1 = elu_f(v1); }
            if (r0 < M) *(float2*)(out + (size_t)r0 * NCOL + col) = make_float2(v0, v1);
            int r1 = r0 + 8;
            float v2 = c[mi][nt][2] * sv.x + hv.x;
            float v3 = c[mi][nt][3] * sv.y + hv.y;
            if (DOELU) { v2 = elu_f(v2); v3 = elu_f(v3); }
            if (r1 < M) *(float2*)(out + (size_t)r1 * NCOL + col) = make_float2(v2, v3);
        }
    }
}

// ---------------- launch ----------------
extern "C" void kernel_launch(void* const* d_in, const int* in_sizes, int n_in,
                              void* d_out, int out_size) {
    const float* x = (const float*)d_in[0];
    const int* ei = (const int*)d_in[1];
    const int N = in_sizes[0] / HDIM;   // 40000
    const int E = in_sizes[1] / 2;      // 600000

    float *hP, *aP, *bP, *esclP, *eshfP;
    float4* wpkP;
    cudaGetSymbolAddress((void**)&hP, g_h);
    cudaGetSymbolAddress((void**)&aP, g_a);
    cudaGetSymbolAddress((void**)&bP, g_b);
    cudaGetSymbolAddress((void**)&wpkP, g_wpk);
    cudaGetSymbolAddress((void**)&esclP, g_escl);
    cudaGetSymbolAddress((void**)&eshfP, g_eshf);

    const int EB = (E + 255) / 256;
    const int NB = (N + 255) / 256;
    const int GM = (N + 127) / 128;
    const int AGB = (N + 7) / 8;

    // CSR build
    k_zero_deg<<<NB, 256>>>(N);
    k_detect<<<1, 32>>>((const unsigned int*)ei);
    k_convcount<<<EB, 256>>>(ei, E);
    k_scan<<<1, 1024>>>(N);
    k_fill<<<EB, 256>>>(E);

    // weight packing + epilogue params
    // stage order: c1w1,c1w2,c2w1,c2w2,c3w1,c3w2,lin1,lin2
    PackArgs pa;
    EpsArgs ea;
    for (int l = 0; l < 3; l++) {
        int base = 2 + l * 8;
        pa.w[2 * l + 0] = (const float*)d_in[base + 0];
        pa.w[2 * l + 1] = (const float*)d_in[base + 6];
        // stage 2l: bias=b1, BN params
        ea.bias[2 * l] = (const float*)d_in[base + 1];
        ea.gam[2 * l]  = (const float*)d_in[base + 2];
        ea.bet[2 * l]  = (const float*)d_in[base + 3];
        ea.mu[2 * l]   = (const float*)d_in[base + 4];
        ea.var[2 * l]  = (const float*)d_in[base + 5];
        ea.epi[2 * l] = 0; ea.n[2 * l] = 128;
        // stage 2l+1: bias=b2 only
        ea.bias[2 * l + 1] = (const float*)d_in[base + 7];
        ea.gam[2 * l + 1] = ea.bet[2 * l + 1] = ea.mu[2 * l + 1] =
            ea.var[2 * l + 1] = (const float*)d_in[base + 7];
        ea.epi[2 * l + 1] = 1; ea.n[2 * l + 1] = 128;
    }
    pa.w[6] = (const float*)d_in[26];
    pa.w[7] = (const float*)d_in[28];
    ea.bias[6] = (const float*)d_in[27];
    ea.gam[6] = ea.bet[6] = ea.mu[6] = ea.var[6] = ea.bias[6];
    ea.epi[6] = 1; ea.n[6] = 128;
    ea.bias[7] = (const float*)d_in[29];
    ea.gam[7] = ea.bet[7] = ea.mu[7] = ea.var[7] = ea.bias[7];
    ea.epi[7] = 1; ea.n[7] = 64;

    k_pack<<<240, 256>>>(pa);
    k_eps<<<8, 128>>>(ea);

    // 3x GINConv
    const float* cur = x;
    for (int l = 0; l < 3; l++) {
        k_agg<<<AGB, 256>>>(cur, aP, N);
        k_tgemm<16, true><<<GM, 128>>>(aP, wpkP + (size_t)(2 * l) * 8192,
                                       esclP + (2 * l) * 128, eshfP + (2 * l) * 128, bP, N);
        k_tgemm<16, true><<<GM, 128>>>(bP, wpkP + (size_t)(2 * l + 1) * 8192,
                                       esclP + (2 * l + 1) * 128, eshfP + (2 * l + 1) * 128, hP, N);
        cur = hP;
    }

    // lin1 + ELU
    k_tgemm<16, true><<<GM, 128>>>(hP, wpkP + (size_t)6 * 8192,
                                   esclP + 6 * 128, eshfP + 6 * 128, aP, N);
    // lin2 (128 -> 64), no ELU
    k_tgemm<8, false><<<GM, 128>>>(aP, wpkP + (size_t)7 * 8192,
                                   esclP + 7 * 128, eshfP + 7 * 128, (float*)d_out, N);
}

// round 6
// speedup vs baseline: 1.9595x; 1.2175x over previous
#include <cuda_runtime.h>
#include <math.h>

#define NMAX 40960
#define EMAX 602112
#define HDIM 128

// ---------------- scratch (device globals: allocation-free) ----------------
__device__ __align__(16) float g_h[NMAX * HDIM];
__device__ __align__(16) float g_a[NMAX * HDIM];
__device__ __align__(16) float g_b[NMAX * HDIM];
__device__ int g_src[EMAX];
__device__ int g_dst[EMAX];
__device__ int g_eidx[EMAX];
__device__ int g_deg[NMAX];
__device__ int g_rowptr[NMAX + 1];
__device__ int g_fill[NMAX];
__device__ int g_is64;
__device__ int g_bsum[64];
__device__ int g_boff[64];
// packed tf32 hi/lo weight fragments: stages 0..6 are 128x128 (8192 float4 each),
// stage 7 is 128x64 (4096 float4). total 61440 float4.
__device__ __align__(16) float4 g_wpk[61440];
__device__ float g_escl[8][128];
__device__ float g_eshf[8][128];

// ---------------- helpers ----------------
__device__ __forceinline__ unsigned tf32r(float f) {
    unsigned u;
    asm("cvt.rna.tf32.f32 %0, %1;" : "=r"(u) : "f"(f));
    return u;
}

__device__ __forceinline__ void mma_tf32(float* c, const unsigned* a,
                                         unsigned b0, unsigned b1) {
    asm volatile(
        "mma.sync.aligned.m16n8k8.row.col.f32.tf32.tf32.f32 "
        "{%0,%1,%2,%3}, {%4,%5,%6,%7}, {%8,%9}, {%0,%1,%2,%3};\n"
        : "+f"(c[0]), "+f"(c[1]), "+f"(c[2]), "+f"(c[3])
        : "r"(a[0]), "r"(a[1]), "r"(a[2]), "r"(a[3]), "r"(b0), "r"(b1));
}

__device__ __forceinline__ float elu_f(float x) { return x > 0.f ? x : expm1f(x); }

// ---------------- edge dtype detection ----------------
__global__ void k_detect(const unsigned int* __restrict__ w) {
    if (threadIdx.x == 0 && blockIdx.x == 0) {
        int ok = 1;
        for (int i = 0; i < 64; i++)
            if (w[2 * i + 1] != 0u) ok = 0;
        g_is64 = ok;
    }
}

__global__ void k_zero_deg(int N) {
    int i = blockIdx.x * blockDim.x + threadIdx.x;
    if (i < N) g_deg[i] = 0;
}

// convert + degree count fused
__global__ void k_convcount(const int* __restrict__ w, int E) {
    int i = blockIdx.x * blockDim.x + threadIdx.x;
    if (i >= E) return;
    int s, d;
    if (g_is64) { s = w[2 * i]; d = w[2 * (E + i)]; }
    else        { s = w[i];     d = w[E + i]; }
    g_src[i] = s;
    g_dst[i] = d;
    atomicAdd(&g_deg[d], 1);
}

// ---------------- 3-phase multi-block exclusive scan ----------------
// Phase A: per-block sum of 1024 degrees
__global__ void k_bsum(int N) {
    int i = blockIdx.x * 1024 + threadIdx.x;
    int v = (i < N) ? g_deg[i] : 0;
#pragma unroll
    for (int o = 16; o; o >>= 1) v += __shfl_down_sync(~0u, v, o);
    __shared__ int ws[32];
    if ((threadIdx.x & 31) == 0) ws[threadIdx.x >> 5] = v;
    __syncthreads();
    if (threadIdx.x < 32) {
        int t = ws[threadIdx.x];
#pragma unroll
        for (int o = 16; o; o >>= 1) t += __shfl_down_sync(~0u, t, o);
        if (threadIdx.x == 0) g_bsum[blockIdx.x] = t;
    }
}

// Phase B: serial scan of <=64 block sums (trivial)
__global__ void k_bscan(int nb, int N) {
    if (threadIdx.x == 0) {
        int run = 0;
        for (int b = 0; b < nb; b++) { g_boff[b] = run; run += g_bsum[b]; }
        g_rowptr[N] = run;
    }
}

// Phase C: block-local exclusive scan + global offset; writes rowptr and fill
__global__ void k_bscatter(int N) {
    int tid = threadIdx.x;
    int i = blockIdx.x * 1024 + tid;
    int v = (i < N) ? g_deg[i] : 0;
    int lane = tid & 31, w = tid >> 5;
    int incl = v;
#pragma unroll
    for (int o = 1; o < 32; o <<= 1) {
        int t = __shfl_up_sync(~0u, incl, o);
        if (lane >= o) incl += t;
    }
    __shared__ int ws[32];
    if (lane == 31) ws[w] = incl;
    __syncthreads();
    if (w == 0) {
        int t = ws[lane];
#pragma unroll
        for (int o = 1; o < 32; o <<= 1) {
            int u = __shfl_up_sync(~0u, t, o);
            if (lane >= o) t += u;
        }
        ws[lane] = t;
    }
    __syncthreads();
    int excl = incl - v + (w > 0 ? ws[w - 1] : 0) + g_boff[blockIdx.x];
    if (i < N) { g_rowptr[i] = excl; g_fill[i] = excl; }
}

__global__ void k_fill(int E) {
    int i = blockIdx.x * blockDim.x + threadIdx.x;
    if (i >= E) return;
    int pos = atomicAdd(&g_fill[g_dst[i]], 1);
    g_eidx[pos] = g_src[i];
}

// ---------------- aggregation: out[i] = x[i] + sum_{j in N(i)} x[j] ----------------
// one warp per node, lane = one float4 of the row; 4x unrolled for MLP
__global__ void __launch_bounds__(256) k_agg(const float* __restrict__ xin,
                                             float* __restrict__ out, int N) {
    int warp = (blockIdx.x * blockDim.x + threadIdx.x) >> 5;
    int lane = threadIdx.x & 31;
    if (warp >= N) return;
    const float4* xv = (const float4*)xin;
    float4 acc = xv[(size_t)warp * 32 + lane];
    int e = g_rowptr[warp];
    int end = g_rowptr[warp + 1];
    for (; e + 4 <= end; e += 4) {
        int s0 = g_eidx[e], s1 = g_eidx[e + 1], s2 = g_eidx[e + 2], s3 = g_eidx[e + 3];
        float4 v0 = xv[(size_t)s0 * 32 + lane];
        float4 v1 = xv[(size_t)s1 * 32 + lane];
        float4 v2 = xv[(size_t)s2 * 32 + lane];
        float4 v3 = xv[(size_t)s3 * 32 + lane];
        acc.x += v0.x + v1.x + v2.x + v3.x;
        acc.y += v0.y + v1.y + v2.y + v3.y;
        acc.z += v0.z + v1.z + v2.z + v3.z;
        acc.w += v0.w + v1.w + v2.w + v3.w;
    }
    for (; e < end; e++) {
        int s = g_eidx[e];
        float4 v = xv[(size_t)s * 32 + lane];
        acc.x += v.x; acc.y += v.y; acc.z += v.z; acc.w += v.w;
    }
    ((float4*)out)[(size_t)warp * 32 + lane] = acc;
}

// ---------------- weight packing: fragment-ordered tf32 hi/lo ----------------
struct PackArgs { const float* w[8]; };

__global__ void k_pack(PackArgs pa) {
    int fid = blockIdx.x * 256 + threadIdx.x;
    if (fid >= 61440) return;
    int s, rem, NTl;
    if (fid < 57344) { s = fid >> 13; rem = fid & 8191; NTl = 16; }
    else             { s = 7; rem = fid - 57344; NTl = 8; }
    int lane = rem & 31;
    int nt = (rem >> 5) % NTl;
    int kt = rem / (32 * NTl);
    int t = lane & 3, g = lane >> 2;
    int Ncol = NTl * 8;
    const float* W = pa.w[s];
    float b0 = W[(kt * 8 + t) * Ncol + nt * 8 + g];
    float b1 = W[(kt * 8 + t + 4) * Ncol + nt * 8 + g];
    unsigned h0 = tf32r(b0);
    unsigned l0 = tf32r(b0 - __uint_as_float(h0));
    unsigned h1 = tf32r(b1);
    unsigned l1 = tf32r(b1 - __uint_as_float(h1));
    g_wpk[fid] = make_float4(__uint_as_float(h0), __uint_as_float(h1),
                             __uint_as_float(l0), __uint_as_float(l1));
}

// ---------------- epilogue param precompute ----------------
struct EpsArgs {
    const float* bias[8];
    const float* gam[8];
    const float* bet[8];
    const float* mu[8];
    const float* var[8];
    int epi[8];
    int n[8];
};

__global__ void k_eps(EpsArgs ea) {
    int s = blockIdx.x;
    int c = threadIdx.x;
    if (c >= ea.n[s]) return;
    if (ea.epi[s] == 0) {
        float sc = ea.gam[s][c] * rsqrtf(ea.var[s][c] + 1e-5f);
        g_escl[s][c] = sc;
        g_eshf[s][c] = (ea.bias[s][c] - ea.mu[s][c]) * sc + ea.bet[s][c];
    } else {
        g_escl[s][c] = 1.f;
        g_eshf[s][c] = ea.bias[s][c];
    }
}

// ---------------- tensor-core GEMM (tf32 x3) + fused epilogue ----------------
// out[M, NTT*8] = elu?(scl * (A[M,128] @ W) + shf)
// 256 threads = 8 warps. warp w: rows (w&3)*32..+32 (2 m16 tiles),
// column half (w>>2) of NTT/2 n8-tiles. Accumulators: 2*(NTT/2)*4 regs.
template <int NTT, bool DOELU>
__global__ void __launch_bounds__(256) k_tgemm(
    const float* __restrict__ A, const float4* __restrict__ WP4,
    const float* __restrict__ scl, const float* __restrict__ shf,
    float* __restrict__ out, int M)
{
    constexpr int NTW = NTT / 2;
    const int warp = threadIdx.x >> 5;
    const int lane = threadIdx.x & 31;
    const int g = lane >> 2, t = lane & 3;
    const int mwarp = warp & 3;
    const int colh = warp >> 2;
    const int R = blockIdx.x * 128 + mwarp * 32;
    const int NCOL = NTT * 8;

    float c[2][NTW][4];
#pragma unroll
    for (int mi = 0; mi < 2; mi++)
#pragma unroll
        for (int nt = 0; nt < NTW; nt++)
#pragma unroll
            for (int j = 0; j < 4; j++) c[mi][nt][j] = 0.f;

#pragma unroll 4
    for (int kt = 0; kt < 16; kt++) {
        unsigned ah[2][4], al[2][4];
#pragma unroll
        for (int mi = 0; mi < 2; mi++) {
            const float* Ap = A + (size_t)(R + mi * 16 + g) * 128 + kt * 8 + t;
            float a0 = Ap[0];
            float a1 = Ap[8 * 128];
            float a2 = Ap[4];
            float a3 = Ap[8 * 128 + 4];
            ah[mi][0] = tf32r(a0); al[mi][0] = tf32r(a0 - __uint_as_float(ah[mi][0]));
            ah[mi][1] = tf32r(a1); al[mi][1] = tf32r(a1 - __uint_as_float(ah[mi][1]));
            ah[mi][2] = tf32r(a2); al[mi][2] = tf32r(a2 - __uint_as_float(ah[mi][2]));
            ah[mi][3] = tf32r(a3); al[mi][3] = tf32r(a3 - __uint_as_float(ah[mi][3]));
        }
        const float4* wp = WP4 + (size_t)kt * NTT * 32 + (size_t)colh * NTW * 32 + lane;
#pragma unroll
        for (int nt = 0; nt < NTW; nt++) {
            float4 b = __ldg(&wp[nt * 32]);
            unsigned bh0 = __float_as_uint(b.x), bh1 = __float_as_uint(b.y);
            unsigned bl0 = __float_as_uint(b.z), bl1 = __float_as_uint(b.w);
#pragma unroll
            for (int mi = 0; mi < 2; mi++) {
                mma_tf32(c[mi][nt], ah[mi], bh0, bh1);
                mma_tf32(c[mi][nt], al[mi], bh0, bh1);
                mma_tf32(c[mi][nt], ah[mi], bl0, bl1);
            }
        }
    }

    // epilogue
#pragma unroll
    for (int nt = 0; nt < NTW; nt++) {
        int col = (colh * NTW + nt) * 8 + 2 * t;
        float2 sv = *(const float2*)(scl + col);
        float2 hv = *(const float2*)(shf + col);
#pragma unroll
        for (int mi = 0; mi < 2; mi++) {
            int r0 = R + mi * 16 + g;
            float v0 = c[mi][nt][0] * sv.x + hv.x;
            float v1 = c[mi][nt][1] * sv.y + hv.y;
            if (DOELU) { v0 = elu_f(v0); v1 = elu_f(v1); }
            if (r0 < M) *(float2*)(out + (size_t)r0 * NCOL + col) = make_float2(v0, v1);
            int r1 = r0 + 8;
            float v2 = c[mi][nt][2] * sv.x + hv.x;
            float v3 = c[mi][nt][3] * sv.y + hv.y;
            if (DOELU) { v2 = elu_f(v2); v3 = elu_f(v3); }
            if (r1 < M) *(float2*)(out + (size_t)r1 * NCOL + col) = make_float2(v2, v3);
        }
    }
}

// ---------------- launch ----------------
extern "C" void kernel_launch(void* const* d_in, const int* in_sizes, int n_in,
                              void* d_out, int out_size) {
    const float* x = (const float*)d_in[0];
    const int* ei = (const int*)d_in[1];
    const int N = in_sizes[0] / HDIM;   // 40000
    const int E = in_sizes[1] / 2;      // 600000

    float *hP, *aP, *bP, *esclP, *eshfP;
    float4* wpkP;
    cudaGetSymbolAddress((void**)&hP, g_h);
    cudaGetSymbolAddress((void**)&aP, g_a);
    cudaGetSymbolAddress((void**)&bP, g_b);
    cudaGetSymbolAddress((void**)&wpkP, g_wpk);
    cudaGetSymbolAddress((void**)&esclP, g_escl);
    cudaGetSymbolAddress((void**)&eshfP, g_eshf);

    const int EB = (E + 255) / 256;
    const int NB = (N + 255) / 256;
    const int SB = (N + 1023) / 1024;   // scan blocks
    const int GM = (N + 127) / 128;
    const int AGB = (N + 7) / 8;

    // CSR build
    k_zero_deg<<<NB, 256>>>(N);
    k_detect<<<1, 32>>>((const unsigned int*)ei);
    k_convcount<<<EB, 256>>>(ei, E);
    k_bsum<<<SB, 1024>>>(N);
    k_bscan<<<1, 32>>>(SB, N);
    k_bscatter<<<SB, 1024>>>(N);
    k_fill<<<EB, 256>>>(E);

    // weight packing + epilogue params
    PackArgs pa;
    EpsArgs ea;
    for (int l = 0; l < 3; l++) {
        int base = 2 + l * 8;
        pa.w[2 * l + 0] = (const float*)d_in[base + 0];
        pa.w[2 * l + 1] = (const float*)d_in[base + 6];
        ea.bias[2 * l] = (const float*)d_in[base + 1];
        ea.gam[2 * l]  = (const float*)d_in[base + 2];
        ea.bet[2 * l]  = (const float*)d_in[base + 3];
        ea.mu[2 * l]   = (const float*)d_in[base + 4];
        ea.var[2 * l]  = (const float*)d_in[base + 5];
        ea.epi[2 * l] = 0; ea.n[2 * l] = 128;
        ea.bias[2 * l + 1] = (const float*)d_in[base + 7];
        ea.gam[2 * l + 1] = ea.bet[2 * l + 1] = ea.mu[2 * l + 1] =
            ea.var[2 * l + 1] = (const float*)d_in[base + 7];
        ea.epi[2 * l + 1] = 1; ea.n[2 * l + 1] = 128;
    }
    pa.w[6] = (const float*)d_in[26];
    pa.w[7] = (const float*)d_in[28];
    ea.bias[6] = (const float*)d_in[27];
    ea.gam[6] = ea.bet[6] = ea.mu[6] = ea.var[6] = ea.bias[6];
    ea.epi[6] = 1; ea.n[6] = 128;
    ea.bias[7] = (const float*)d_in[29];
    ea.gam[7] = ea.bet[7] = ea.mu[7] = ea.var[7] = ea.bias[7];
    ea.epi[7] = 1; ea.n[7] = 64;

    k_pack<<<240, 256>>>(pa);
    k_eps<<<8, 128>>>(ea);

    // 3x GINConv
    const float* cur = x;
    for (int l = 0; l < 3; l++) {
        k_agg<<<AGB, 256>>>(cur, aP, N);
        k_tgemm<16, true><<<GM, 256>>>(aP, wpkP + (size_t)(2 * l) * 8192,
                                       esclP + (2 * l) * 128, eshfP + (2 * l) * 128, bP, N);
        k_tgemm<16, true><<<GM, 256>>>(bP, wpkP + (size_t)(2 * l + 1) * 8192,
                                       esclP + (2 * l + 1) * 128, eshfP + (2 * l + 1) * 128, hP, N);
        cur = hP;
    }

    // lin1 + ELU
    k_tgemm<16, true><<<GM, 256>>>(hP, wpkP + (size_t)6 * 8192,
                                   esclP + 6 * 128, eshfP + 6 * 128, aP, N);
    // lin2 (128 -> 64), no ELU
    k_tgemm<8, false><<<GM, 256>>>(aP, wpkP + (size_t)7 * 8192,
                                   esclP + 7 * 128, eshfP + 7 * 128, (float*)d_out, N);
}

// round 9
// speedup vs baseline: 3.0492x; 1.5561x over previous
#include <cuda_runtime.h>
#include <math.h>

#define NMAX 40960
#define EMAX 602112
#define HDIM 128

// ---------------- scratch (device globals: allocation-free) ----------------
__device__ __align__(16) float g_h[NMAX * HDIM];
__device__ __align__(16) float g_a[NMAX * HDIM];
__device__ __align__(16) float g_b[NMAX * HDIM];
__device__ int g_src[EMAX];
__device__ int g_dst[EMAX];
__device__ int g_eidx[EMAX];
__device__ int g_deg[NMAX];
__device__ int g_rowptr[NMAX + 1];
__device__ int g_fill[NMAX];
__device__ int g_is64;
__device__ volatile unsigned g_sflag[64];   // lookback: (state<<30)|sum, UNSIGNED
// packed bf16 hi/lo weight fragments (m16n8k16):
// stages 0..6: 128x128 -> 8 kt * 16 nt * 32 lanes = 4096 float4 each
// stage 7: 128x64 -> 2048 float4. total 30720.
__device__ __align__(16) float4 g_wpk[30720];
__device__ float g_escl[8][128];
__device__ float g_eshf[8][128];

// ---------------- helpers ----------------
__device__ __forceinline__ unsigned packbf(float hi, float lo) {
    unsigned r;
    asm("cvt.rn.bf16x2.f32 %0, %1, %2;" : "=r"(r) : "f"(hi), "f"(lo));
    return r;
}
__device__ __forceinline__ float lo_f(unsigned p) { return __uint_as_float(p << 16); }
__device__ __forceinline__ float hi_f(unsigned p) { return __uint_as_float(p & 0xffff0000u); }

// pack hi bf16x2 of (l,h) and residual lo bf16x2; lo half = first-k element
__device__ __forceinline__ void split2(float l, float h, unsigned& phi, unsigned& plo) {
    phi = packbf(h, l);
    plo = packbf(h - hi_f(phi), l - lo_f(phi));
}

__device__ __forceinline__ void mma_bf16(float* c, const unsigned* a,
                                         unsigned b0, unsigned b1) {
    asm volatile(
        "mma.sync.aligned.m16n8k16.row.col.f32.bf16.bf16.f32 "
        "{%0,%1,%2,%3}, {%4,%5,%6,%7}, {%8,%9}, {%0,%1,%2,%3};\n"
        : "+f"(c[0]), "+f"(c[1]), "+f"(c[2]), "+f"(c[3])
        : "r"(a[0]), "r"(a[1]), "r"(a[2]), "r"(a[3]), "r"(b0), "r"(b1));
}

__device__ __forceinline__ float elu_f(float x) { return x > 0.f ? x : expm1f(x); }

// ---------------- merged prep kernel ----------------
// blocks 0..119   : weight packing (30720 float4)
// block  120      : epilogue params
// blocks 121..280 : zero g_deg
// block  281      : zero lookback flags + edge dtype detect
struct PrepArgs {
    const float* w[8];
    const float* bias[8];
    const float* gam[8];
    const float* bet[8];
    const float* mu[8];
    const float* var[8];
    int epi[8];
    const unsigned* ei;
    int N;
};

__global__ void k_prep(PrepArgs pa) {
    int blk = blockIdx.x, tid = threadIdx.x;
    if (blk < 120) {
        int fid = blk * 256 + tid;           // < 30720
        int s, rem, NTl;
        if (fid < 28672) { s = fid >> 12; rem = fid & 4095; NTl = 16; }
        else             { s = 7; rem = fid - 28672; NTl = 8; }
        int lane = rem & 31;
        int nt = (rem >> 5) % NTl;
        int kt = rem / (32 * NTl);
        int t = lane & 3, g = lane >> 2;
        int Ncol = NTl * 8;
        int n = nt * 8 + g;
        const float* W = pa.w[s];
        int k0 = kt * 16 + 2 * t;
        float w00 = W[(k0 + 0) * Ncol + n];
        float w01 = W[(k0 + 1) * Ncol + n];
        float w10 = W[(k0 + 8) * Ncol + n];
        float w11 = W[(k0 + 9) * Ncol + n];
        unsigned h0, l0, h1, l1;
        split2(w00, w01, h0, l0);
        split2(w10, w11, h1, l1);
        g_wpk[fid] = make_float4(__uint_as_float(h0), __uint_as_float(h1),
                                 __uint_as_float(l0), __uint_as_float(l1));
    } else if (blk == 120) {
        for (int idx = tid; idx < 1024; idx += 256) {
            int s = idx >> 7, c = idx & 127;
            if (s == 7 && c >= 64) continue;
            if (pa.epi[s] == 0) {
                float sc = pa.gam[s][c] * rsqrtf(pa.var[s][c] + 1e-5f);
                g_escl[s][c] = sc;
                g_eshf[s][c] = (pa.bias[s][c] - pa.mu[s][c]) * sc + pa.bet[s][c];
            } else {
                g_escl[s][c] = 1.f;
                g_eshf[s][c] = pa.bias[s][c];
            }
        }
    } else if (blk < 281) {
        int i = (blk - 121) * 256 + tid;
        if (i < pa.N) g_deg[i] = 0;
    } else {
        if (tid < 64) *(unsigned*)&g_sflag[tid] = 0u;
        if (tid == 0) {
            int ok = 1;
            for (int i = 0; i < 64; i++)
                if (pa.ei[2 * i + 1] != 0u) ok = 0;
            g_is64 = ok;
        }
    }
}

// ---------------- convert + degree count ----------------
__global__ void k_convcount(const int* __restrict__ w, int E) {
    int i = blockIdx.x * blockDim.x + threadIdx.x;
    if (i >= E) return;
    int s, d;
    if (g_is64) { s = w[2 * i]; d = w[2 * (E + i)]; }
    else        { s = w[i];     d = w[E + i]; }
    g_src[i] = s;
    g_dst[i] = d;
    atomicAdd(&g_deg[d], 1);
}

// ---------------- single-kernel decoupled-lookback exclusive scan ----------------
// grid <= 64 blocks of 1024 (all co-resident on 148 SMs -> forward progress).
// Single-word protocol: state in bits 31:30 (1=aggregate, 2=prefix), sum in 29:0.
// All UNSIGNED so (f >> 30) is a logical shift (state 2 compares as 2, not -2).
__global__ void __launch_bounds__(1024) k_scan2(int N) {
    int b = blockIdx.x, tid = threadIdx.x;
    int i = b * 1024 + tid;
    int v = (i < N) ? g_deg[i] : 0;
    int lane = tid & 31, w = tid >> 5;
    int incl = v;
#pragma unroll
    for (int o = 1; o < 32; o <<= 1) {
        int t = __shfl_up_sync(~0u, incl, o);
        if (lane >= o) incl += t;
    }
    __shared__ int ws[32];
    __shared__ int s_prefix;
    if (lane == 31) ws[w] = incl;
    __syncthreads();
    if (w == 0) {
        int t = ws[lane];
#pragma unroll
        for (int o = 1; o < 32; o <<= 1) {
            int u = __shfl_up_sync(~0u, t, o);
            if (lane >= o) t += u;
        }
        ws[lane] = t;
    }
    __syncthreads();
    int bincl = incl + (w > 0 ? ws[w - 1] : 0);
    unsigned btot = (unsigned)ws[31];

    if (tid == 0) {
        if (b == 0) {
            s_prefix = 0;
            atomicExch((unsigned*)&g_sflag[0], (2u << 30) | btot);
        } else {
            atomicExch((unsigned*)&g_sflag[b], (1u << 30) | btot);
            unsigned excl = 0;
            int j = b - 1;
            while (true) {
                unsigned f;
                do { f = g_sflag[j]; } while ((f >> 30) == 0u);
                excl += f & 0x3fffffffu;
                if ((f >> 30) == 2u) break;
                j--;
            }
            s_prefix = (int)excl;
            atomicExch((unsigned*)&g_sflag[b], (2u << 30) | (excl + btot));
        }
    }
    __syncthreads();
    int excl_i = bincl - v + s_prefix;
    if (i < N) {
        g_rowptr[i] = excl_i;
        g_fill[i] = excl_i;
        if (i == N - 1) g_rowptr[N] = excl_i + v;
    }
}

__global__ void k_fill(int E) {
    int i = blockIdx.x * blockDim.x + threadIdx.x;
    if (i >= E) return;
    int pos = atomicAdd(&g_fill[g_dst[i]], 1);
    g_eidx[pos] = g_src[i];
}

// ---------------- aggregation: out[i] = x[i] + sum_{j in N(i)} x[j] ----------------
__global__ void __launch_bounds__(256) k_agg(const float* __restrict__ xin,
                                             float* __restrict__ out, int N) {
    int warp = (blockIdx.x * blockDim.x + threadIdx.x) >> 5;
    int lane = threadIdx.x & 31;
    if (warp >= N) return;
    const float4* xv = (const float4*)xin;
    float4 acc = xv[(size_t)warp * 32 + lane];
    int e = g_rowptr[warp];
    int end = g_rowptr[warp + 1];
    for (; e + 4 <= end; e += 4) {
        int s0 = g_eidx[e], s1 = g_eidx[e + 1], s2 = g_eidx[e + 2], s3 = g_eidx[e + 3];
        float4 v0 = xv[(size_t)s0 * 32 + lane];
        float4 v1 = xv[(size_t)s1 * 32 + lane];
        float4 v2 = xv[(size_t)s2 * 32 + lane];
        float4 v3 = xv[(size_t)s3 * 32 + lane];
        acc.x += v0.x + v1.x + v2.x + v3.x;
        acc.y += v0.y + v1.y + v2.y + v3.y;
        acc.z += v0.z + v1.z + v2.z + v3.z;
        acc.w += v0.w + v1.w + v2.w + v3.w;
    }
    for (; e < end; e++) {
        int s = g_eidx[e];
        float4 v = xv[(size_t)s * 32 + lane];
        acc.x += v.x; acc.y += v.y; acc.z += v.z; acc.w += v.w;
    }
    ((float4*)out)[(size_t)warp * 32 + lane] = acc;
}

// ---------------- bf16x3 tensor-core GEMM (m16n8k16) + fused epilogue ----------------
// out[M, NTT*8] = elu?(scl * (A[M,128] @ W) + shf)
// 256 threads = 8 warps. warp w: rows (w&3)*32 (2 m16 tiles), column half (w>>2).
template <int NTT, bool DOELU>
__global__ void __launch_bounds__(256, 2) k_bgemm(
    const float* __restrict__ A, const float4* __restrict__ WP4,
    const float* __restrict__ scl, const float* __restrict__ shf,
    float* __restrict__ out, int M)
{
    constexpr int NTW = NTT / 2;
    const int warp = threadIdx.x >> 5;
    const int lane = threadIdx.x & 31;
    const int g = lane >> 2, t = lane & 3;
    const int mwarp = warp & 3;
    const int colh = warp >> 2;
    const int R = blockIdx.x * 128 + mwarp * 32;
    const int NCOL = NTT * 8;

    float c[2][NTW][4];
#pragma unroll
    for (int mi = 0; mi < 2; mi++)
#pragma unroll
        for (int nt = 0; nt < NTW; nt++)
#pragma unroll
            for (int j = 0; j < 4; j++) c[mi][nt][j] = 0.f;

#pragma unroll 4
    for (int kt = 0; kt < 8; kt++) {      // K = 128 = 8 x k16
        unsigned ah[2][4], al[2][4];
#pragma unroll
        for (int mi = 0; mi < 2; mi++) {
            const float* Ap = A + (size_t)(R + mi * 16 + g) * 128 + kt * 16 + 2 * t;
            float2 f0 = *(const float2*)(Ap);             // row g,   k 2t,2t+1
            float2 f1 = *(const float2*)(Ap + 8 * 128);   // row g+8, k 2t,2t+1
            float2 f2 = *(const float2*)(Ap + 8);         // row g,   k 2t+8,2t+9
            float2 f3 = *(const float2*)(Ap + 8 * 128 + 8);
            split2(f0.x, f0.y, ah[mi][0], al[mi][0]);
            split2(f1.x, f1.y, ah[mi][1], al[mi][1]);
            split2(f2.x, f2.y, ah[mi][2], al[mi][2]);
            split2(f3.x, f3.y, ah[mi][3], al[mi][3]);
        }
        const float4* wp = WP4 + (size_t)kt * NTT * 32 + (size_t)colh * NTW * 32 + lane;
#pragma unroll
        for (int nt = 0; nt < NTW; nt++) {
            float4 b = __ldg(&wp[nt * 32]);
            unsigned bh0 = __float_as_uint(b.x), bh1 = __float_as_uint(b.y);
            unsigned bl0 = __float_as_uint(b.z), bl1 = __float_as_uint(b.w);
#pragma unroll
            for (int mi = 0; mi < 2; mi++) {
                mma_bf16(c[mi][nt], ah[mi], bh0, bh1);   // hi*hi
                mma_bf16(c[mi][nt], al[mi], bh0, bh1);   // lo*hi
                mma_bf16(c[mi][nt], ah[mi], bl0, bl1);   // hi*lo
            }
        }
    }

    // epilogue (C frag: c0,c1 -> row g, cols 2t..; c2,c3 -> row g+8)
#pragma unroll
    for (int nt = 0; nt < NTW; nt++) {
        int col = (colh * NTW + nt) * 8 + 2 * t;
        float2 sv = *(const float2*)(scl + col);
        float2 hv = *(const float2*)(shf + col);
#pragma unroll
        for (int mi = 0; mi < 2; mi++) {
            int r0 = R + mi * 16 + g;
            float v0 = c[mi][nt][0] * sv.x + hv.x;
            float v1 = c[mi][nt][1] * sv.y + hv.y;
            if (DOELU) { v0 = elu_f(v0); v1 = elu_f(v1); }
            if (r0 < M) *(float2*)(out + (size_t)r0 * NCOL + col) = make_float2(v0, v1);
            int r1 = r0 + 8;
            float v2 = c[mi][nt][2] * sv.x + hv.x;
            float v3 = c[mi][nt][3] * sv.y + hv.y;
            if (DOELU) { v2 = elu_f(v2); v3 = elu_f(v3); }
            if (r1 < M) *(float2*)(out + (size_t)r1 * NCOL + col) = make_float2(v2, v3);
        }
    }
}

// ---------------- launch ----------------
extern "C" void kernel_launch(void* const* d_in, const int* in_sizes, int n_in,
                              void* d_out, int out_size) {
    const float* x = (const float*)d_in[0];
    const int* ei = (const int*)d_in[1];
    const int N = in_sizes[0] / HDIM;   // 40000
    const int E = in_sizes[1] / 2;      // 600000

    float *hP, *aP, *bP, *esclP, *eshfP;
    float4* wpkP;
    cudaGetSymbolAddress((void**)&hP, g_h);
    cudaGetSymbolAddress((void**)&aP, g_a);
    cudaGetSymbolAddress((void**)&bP, g_b);
    cudaGetSymbolAddress((void**)&wpkP, g_wpk);
    cudaGetSymbolAddress((void**)&esclP, g_escl);
    cudaGetSymbolAddress((void**)&eshfP, g_eshf);

    const int EB = (E + 255) / 256;
    const int SB = (N + 1023) / 1024;   // scan blocks (<=64, all co-resident)
    const int GM = (N + 127) / 128;
    const int AGB = (N + 7) / 8;

    // prep args
    PrepArgs pa;
    for (int l = 0; l < 3; l++) {
        int base = 2 + l * 8;
        pa.w[2 * l + 0] = (const float*)d_in[base + 0];
        pa.w[2 * l + 1] = (const float*)d_in[base + 6];
        pa.bias[2 * l] = (const float*)d_in[base + 1];
        pa.gam[2 * l]  = (const float*)d_in[base + 2];
        pa.bet[2 * l]  = (const float*)d_in[base + 3];
        pa.mu[2 * l]   = (const float*)d_in[base + 4];
        pa.var[2 * l]  = (const float*)d_in[base + 5];
        pa.epi[2 * l] = 0;
        pa.bias[2 * l + 1] = (const float*)d_in[base + 7];
        pa.gam[2 * l + 1] = pa.bet[2 * l + 1] = pa.mu[2 * l + 1] =
            pa.var[2 * l + 1] = (const float*)d_in[base + 7];
        pa.epi[2 * l + 1] = 1;
    }
    pa.w[6] = (const float*)d_in[26];
    pa.w[7] = (const float*)d_in[28];
    pa.bias[6] = (const float*)d_in[27];
    pa.gam[6] = pa.bet[6] = pa.mu[6] = pa.var[6] = pa.bias[6];
    pa.epi[6] = 1;
    pa.bias[7] = (const float*)d_in[29];
    pa.gam[7] = pa.bet[7] = pa.mu[7] = pa.var[7] = pa.bias[7];
    pa.epi[7] = 1;
    pa.ei = (const unsigned*)ei;
    pa.N = N;

    k_prep<<<282, 256>>>(pa);
    k_convcount<<<EB, 256>>>(ei, E);
    k_scan2<<<SB, 1024>>>(N);
    k_fill<<<EB, 256>>>(E);

    const float* cur = x;
    for (int l = 0; l < 3; l++) {
        k_agg<<<AGB, 256>>>(cur, aP, N);
        k_bgemm<16, true><<<GM, 256>>>(aP, wpkP + (size_t)(2 * l) * 4096,
                                       esclP + (2 * l) * 128, eshfP + (2 * l) * 128, bP, N);
        k_bgemm<16, true><<<GM, 256>>>(bP, wpkP + (size_t)(2 * l + 1) * 4096,
                                       esclP + (2 * l + 1) * 128, eshfP + (2 * l + 1) * 128, hP, N);
        cur = hP;
    }

    // lin1 + ELU
    k_bgemm<16, true><<<GM, 256>>>(hP, wpkP + (size_t)6 * 4096,
                                   esclP + 6 * 128, eshfP + 6 * 128, aP, N);
    // lin2 (128 -> 64), no ELU
    k_bgemm<8, false><<<GM, 256>>>(aP, wpkP + (size_t)28672,
                                   esclP + 7 * 128, eshfP + 7 * 128, (float*)d_out, N);
}